// round 1
// baseline (speedup 1.0000x reference)
#include <cuda_runtime.h>

#define FULLMASK 0xffffffffu

__device__ __forceinline__ float shx(float v, int m) {
    return __shfl_xor_sync(FULLMASK, v, m);
}

// State layout: amplitude index i = (lane << 3) | r, r in [0,8).
// Qubit q corresponds to index bit b = 7 - q.
//   b in [0,3): register bit BT of r
//   b in [3,8): lane bit LB = b - 3

// ---------------- RY ----------------
template<int BT>
__device__ __forceinline__ void ry_reg(float ar[8], float ai[8], float c, float s) {
#pragma unroll
    for (int r = 0; r < 8; ++r) {
        if ((r & (1 << BT)) == 0) {
            const int r1 = r | (1 << BT);
            float a0 = ar[r], a1 = ar[r1];
            ar[r]  = c * a0 - s * a1;
            ar[r1] = s * a0 + c * a1;
            a0 = ai[r]; a1 = ai[r1];
            ai[r]  = c * a0 - s * a1;
            ai[r1] = s * a0 + c * a1;
        }
    }
}

template<int LB>
__device__ __forceinline__ void ry_lane(float ar[8], float ai[8], float c, float s, int lane) {
    // new0 = c*a0 - s*a1 ; new1 = s*a0 + c*a1  => new = c*own + (mybit ? +s : -s)*partner
    const float sg = ((lane >> LB) & 1) ? s : -s;
#pragma unroll
    for (int r = 0; r < 8; ++r) {
        float pr = shx(ar[r], 1 << LB);
        float pi = shx(ai[r], 1 << LB);
        ar[r] = fmaf(sg, pr, c * ar[r]);
        ai[r] = fmaf(sg, pi, c * ai[r]);
    }
}

// ---------------- CNOT (swap along target bit where control bit == 1) ----------------
template<int BC, int BT>
__device__ __forceinline__ void cnot_rr(float ar[8], float ai[8]) {
#pragma unroll
    for (int r = 0; r < 8; ++r) {
        if ((r & (1 << BC)) && !(r & (1 << BT))) {
            const int r1 = r | (1 << BT);
            float t = ar[r]; ar[r] = ar[r1]; ar[r1] = t;
            t = ai[r]; ai[r] = ai[r1]; ai[r1] = t;
        }
    }
}

template<int LC, int BT>
__device__ __forceinline__ void cnot_lr(float ar[8], float ai[8], int lane) {
    const bool p = (lane >> LC) & 1;
#pragma unroll
    for (int r = 0; r < 8; ++r) {
        if (!(r & (1 << BT))) {
            const int r1 = r | (1 << BT);
            float t0 = ar[r], t1 = ar[r1];
            ar[r]  = p ? t1 : t0;
            ar[r1] = p ? t0 : t1;
            t0 = ai[r]; t1 = ai[r1];
            ai[r]  = p ? t1 : t0;
            ai[r1] = p ? t0 : t1;
        }
    }
}

template<int BC, int LT>
__device__ __forceinline__ void cnot_rl(float ar[8], float ai[8]) {
#pragma unroll
    for (int r = 0; r < 8; ++r) {
        if (r & (1 << BC)) {       // compile-time: same r set on every lane
            ar[r] = shx(ar[r], 1 << LT);
            ai[r] = shx(ai[r], 1 << LT);
        }
    }
}

template<int LC, int LT>
__device__ __forceinline__ void cnot_ll(float ar[8], float ai[8], int lane) {
    const bool p = (lane >> LC) & 1;   // control bit identical for both lanes of a pair
#pragma unroll
    for (int r = 0; r < 8; ++r) {
        float pr = shx(ar[r], 1 << LT);
        float pi = shx(ai[r], 1 << LT);
        ar[r] = p ? pr : ar[r];
        ai[r] = p ? pi : ai[r];
    }
}

// ---------------- CRX: on control==1 subspace apply [[c,-i s],[-i s,c]], s=sin(th/2) ----------------
// new0.re = c*a0r + s*a1i ; new0.im = c*a0i - s*a1r ; (symmetric for new1)
template<int BC, int BT>
__device__ __forceinline__ void crx_rr(float ar[8], float ai[8], float c, float s) {
#pragma unroll
    for (int r = 0; r < 8; ++r) {
        if ((r & (1 << BC)) && !(r & (1 << BT))) {
            const int r1 = r | (1 << BT);
            float a0r = ar[r], a0i = ai[r], a1r = ar[r1], a1i = ai[r1];
            ar[r]  = fmaf( s, a1i, c * a0r);
            ai[r]  = fmaf(-s, a1r, c * a0i);
            ar[r1] = fmaf( s, a0i, c * a1r);
            ai[r1] = fmaf(-s, a0r, c * a1i);
        }
    }
}

template<int LC, int BT>
__device__ __forceinline__ void crx_lr(float ar[8], float ai[8], float c, float s, int lane) {
    const bool p = (lane >> LC) & 1;
    const float ce = p ? c : 1.0f;
    const float se = p ? s : 0.0f;
#pragma unroll
    for (int r = 0; r < 8; ++r) {
        if (!(r & (1 << BT))) {
            const int r1 = r | (1 << BT);
            float a0r = ar[r], a0i = ai[r], a1r = ar[r1], a1i = ai[r1];
            ar[r]  = fmaf( se, a1i, ce * a0r);
            ai[r]  = fmaf(-se, a1r, ce * a0i);
            ar[r1] = fmaf( se, a0i, ce * a1r);
            ai[r1] = fmaf(-se, a0r, ce * a1i);
        }
    }
}

template<int BC, int LT>
__device__ __forceinline__ void crx_rl(float ar[8], float ai[8], float c, float s) {
    // matrix is symmetric: formula identical for both lanes of a pair
#pragma unroll
    for (int r = 0; r < 8; ++r) {
        if (r & (1 << BC)) {
            float pr = shx(ar[r], 1 << LT);
            float pi = shx(ai[r], 1 << LT);
            float nr = fmaf( s, pi, c * ar[r]);
            float ni = fmaf(-s, pr, c * ai[r]);
            ar[r] = nr; ai[r] = ni;
        }
    }
}

template<int LC, int LT>
__device__ __forceinline__ void crx_ll(float ar[8], float ai[8], float c, float s, int lane) {
    const bool p = (lane >> LC) & 1;
    const float ce = p ? c : 1.0f;
    const float se = p ? s : 0.0f;
#pragma unroll
    for (int r = 0; r < 8; ++r) {
        float pr = shx(ar[r], 1 << LT);
        float pi = shx(ai[r], 1 << LT);
        float nr = fmaf( se, pi, ce * ar[r]);
        float ni = fmaf(-se, pr, ce * ai[r]);
        ar[r] = nr; ai[r] = ni;
    }
}

// ---------------- U3 (general 1-qubit gate) ----------------
template<int BT>
__device__ __forceinline__ void u3_reg(float ar[8], float ai[8],
    float u00r, float u00i, float u01r, float u01i,
    float u10r, float u10i, float u11r, float u11i) {
#pragma unroll
    for (int r = 0; r < 8; ++r) {
        if (!(r & (1 << BT))) {
            const int r1 = r | (1 << BT);
            float a0r = ar[r], a0i = ai[r], a1r = ar[r1], a1i = ai[r1];
            ar[r]  = u00r*a0r - u00i*a0i + u01r*a1r - u01i*a1i;
            ai[r]  = u00r*a0i + u00i*a0r + u01r*a1i + u01i*a1r;
            ar[r1] = u10r*a0r - u10i*a0i + u11r*a1r - u11i*a1i;
            ai[r1] = u10r*a0i + u10i*a0r + u11r*a1i + u11i*a1r;
        }
    }
}

template<int LT>
__device__ __forceinline__ void u3_lane(float ar[8], float ai[8],
    float u00r, float u00i, float u01r, float u01i,
    float u10r, float u10i, float u11r, float u11i, int lane) {
    const bool p = (lane >> LT) & 1;
    const float cor = p ? u11r : u00r, coi = p ? u11i : u00i;  // coeff of own amp
    const float cpr = p ? u10r : u01r, cpi = p ? u10i : u01i;  // coeff of partner amp
#pragma unroll
    for (int r = 0; r < 8; ++r) {
        float pr = shx(ar[r], 1 << LT);
        float pi = shx(ai[r], 1 << LT);
        float vr = ar[r], vi = ai[r];
        ar[r] = cor*vr - coi*vi + cpr*pr - cpi*pi;
        ai[r] = cor*vi + coi*vr + cpr*pi + cpi*pr;
    }
}

// ==================================================================================
__global__ void __launch_bounds__(256) qcnn_kernel(
    const float* __restrict__ x,
    const float* __restrict__ crx_theta,
    const float* __restrict__ u3p,
    const float* __restrict__ w1,
    const float* __restrict__ b1,
    const float* __restrict__ w2,
    const float* __restrict__ b2,
    float* __restrict__ out, int nB)
{
    const int warp = (blockIdx.x * blockDim.x + threadIdx.x) >> 5;
    if (warp >= nB) return;
    const int lane = threadIdx.x & 31;

    // ---- per-element RY angles (reused across all 4 cycles) ----
    const float4 x0 = reinterpret_cast<const float4*>(x + warp * 8)[0];
    const float4 x1 = reinterpret_cast<const float4*>(x + warp * 8)[1];
    float xs[8] = {x0.x, x0.y, x0.z, x0.w, x1.x, x1.y, x1.z, x1.w};
    float c8[8], s8[8];
#pragma unroll
    for (int q = 0; q < 8; ++q) __sincosf(0.5f * xs[q], &s8[q], &c8[q]);

    // ---- init |0...0> ----
    float ar[8], ai[8];
#pragma unroll
    for (int r = 0; r < 8; ++r) { ar[r] = 0.0f; ai[r] = 0.0f; }
    if (lane == 0) ar[0] = 1.0f;

    // ---- 4 cycles of RY(q) then ring CNOT(q, q+1 mod 8) ----
    // qubit q -> bit 7-q:  q0..q4 = lane bits 4..0 ; q5..q7 = reg bits 2..0
#pragma unroll 1
    for (int cyc = 0; cyc < 4; ++cyc) {
        ry_lane<4>(ar, ai, c8[0], s8[0], lane);
        ry_lane<3>(ar, ai, c8[1], s8[1], lane);
        ry_lane<2>(ar, ai, c8[2], s8[2], lane);
        ry_lane<1>(ar, ai, c8[3], s8[3], lane);
        ry_lane<0>(ar, ai, c8[4], s8[4], lane);
        ry_reg<2>(ar, ai, c8[5], s8[5]);
        ry_reg<1>(ar, ai, c8[6], s8[6]);
        ry_reg<0>(ar, ai, c8[7], s8[7]);

        cnot_ll<4, 3>(ar, ai, lane);   // (q0,q1)
        cnot_ll<3, 2>(ar, ai, lane);   // (q1,q2)
        cnot_ll<2, 1>(ar, ai, lane);   // (q2,q3)
        cnot_ll<1, 0>(ar, ai, lane);   // (q3,q4)
        cnot_lr<0, 2>(ar, ai, lane);   // (q4,q5)
        cnot_rr<2, 1>(ar, ai);         // (q5,q6)
        cnot_rr<1, 0>(ar, ai);         // (q6,q7)
        cnot_rl<0, 4>(ar, ai);         // (q7,q0)
    }

    // ---- layer 0: CRX(theta0) ----
    {
        float s0, c0;
        __sincosf(0.5f * crx_theta[0], &s0, &c0);
        crx_ll<4, 3>(ar, ai, c0, s0, lane);  // (q0,q1)
        crx_ll<2, 1>(ar, ai, c0, s0, lane);  // (q2,q3)
        crx_lr<0, 2>(ar, ai, c0, s0, lane);  // (q4,q5)
        crx_rr<1, 0>(ar, ai, c0, s0);        // (q6,q7)
        crx_ll<3, 2>(ar, ai, c0, s0, lane);  // (q1,q2)
        crx_ll<1, 0>(ar, ai, c0, s0, lane);  // (q3,q4)
        crx_rr<2, 1>(ar, ai, c0, s0);        // (q5,q6)
    }
    // ---- layer 0: U3 on qubits [1,3,5,7] ----
    {
        const float th = u3p[0], ph = u3p[1], lm = u3p[2];
        float st, ct;  __sincosf(0.5f * th, &st, &ct);
        float sl, cl;  __sincosf(lm, &sl, &cl);
        float sp, cp;  __sincosf(ph, &sp, &cp);
        float spl, cpl; __sincosf(ph + lm, &spl, &cpl);
        const float u00r = ct,        u00i = 0.0f;
        const float u01r = -cl * st,  u01i = -sl * st;
        const float u10r =  cp * st,  u10i =  sp * st;
        const float u11r = cpl * ct,  u11i = spl * ct;
        u3_lane<3>(ar, ai, u00r, u00i, u01r, u01i, u10r, u10i, u11r, u11i, lane); // q1
        u3_lane<1>(ar, ai, u00r, u00i, u01r, u01i, u10r, u10i, u11r, u11i, lane); // q3
        u3_reg<2>(ar, ai, u00r, u00i, u01r, u01i, u10r, u10i, u11r, u11i);        // q5
        u3_reg<0>(ar, ai, u00r, u00i, u01r, u01i, u10r, u10i, u11r, u11i);        // q7
    }
    // ---- layer 1: CRX(theta1) on active [1,3,5,7] ----
    {
        float s1, c1;
        __sincosf(0.5f * crx_theta[1], &s1, &c1);
        crx_ll<3, 1>(ar, ai, c1, s1, lane);  // (q1,q3)
        crx_rr<2, 0>(ar, ai, c1, s1);        // (q5,q7)
        crx_lr<1, 2>(ar, ai, c1, s1, lane);  // (q3,q5)
    }
    // ---- layer 1: U3 on qubits [3,7] ----
    {
        const float th = u3p[3], ph = u3p[4], lm = u3p[5];
        float st, ct;  __sincosf(0.5f * th, &st, &ct);
        float sl, cl;  __sincosf(lm, &sl, &cl);
        float sp, cp;  __sincosf(ph, &sp, &cp);
        float spl, cpl; __sincosf(ph + lm, &spl, &cpl);
        const float u00r = ct,        u00i = 0.0f;
        const float u01r = -cl * st,  u01i = -sl * st;
        const float u10r =  cp * st,  u10i =  sp * st;
        const float u11r = cpl * ct,  u11i = spl * ct;
        u3_lane<1>(ar, ai, u00r, u00i, u01r, u01i, u10r, u10i, u11r, u11i, lane); // q3
        u3_reg<0>(ar, ai, u00r, u00i, u01r, u01i, u10r, u10i, u11r, u11i);        // q7
    }

    // ---- expectation values: feats = [<Z_q3>, <Z_q7>] (q3: lane bit 1, q7: reg bit 0) ----
    float sAll = 0.0f, sB0 = 0.0f;
#pragma unroll
    for (int r = 0; r < 8; ++r) {
        float m = ar[r] * ar[r] + ai[r] * ai[r];
        sAll += m;
        sB0 += (r & 1) ? -m : m;
    }
    float f0 = ((lane >> 1) & 1) ? -sAll : sAll;  // <Z> qubit 3
    float f1 = sB0;                               // <Z> qubit 7
#pragma unroll
    for (int m = 16; m >= 1; m >>= 1) {
        f0 += shx(f0, m);
        f1 += shx(f1, m);
    }

    // ---- MLP head: sigmoid(tanh(f @ w1 + b1) @ w2 + b2) ----
    if (lane == 0) {
        float acc = b2[0];
#pragma unroll
        for (int j = 0; j < 10; ++j) {
            float h = tanhf(f0 * w1[j] + f1 * w1[10 + j] + b1[j]);
            acc = fmaf(h, w2[j], acc);
        }
        out[warp] = 1.0f / (1.0f + __expf(-acc));
    }
}

extern "C" void kernel_launch(void* const* d_in, const int* in_sizes, int n_in,
                              void* d_out, int out_size) {
    const float* x         = (const float*)d_in[0];
    const float* crx_theta = (const float*)d_in[1];
    const float* u3_params = (const float*)d_in[2];
    const float* w1        = (const float*)d_in[3];
    const float* b1        = (const float*)d_in[4];
    const float* w2        = (const float*)d_in[5];
    const float* b2        = (const float*)d_in[6];
    float* out = (float*)d_out;

    const int nB = out_size;              // (B, 1) output -> B batch elements
    const int threads = 256;              // 8 warps / block, 1 warp per batch element
    const int blocks = (nB * 32 + threads - 1) / threads;
    qcnn_kernel<<<blocks, threads>>>(x, crx_theta, u3_params, w1, b1, w2, b2, out, nB);
}

// round 2
// speedup vs baseline: 1.8561x; 1.8561x over previous
#include <cuda_runtime.h>

#define FULLMASK 0xffffffffu

__device__ __forceinline__ float shx(float v, int m) {
    return __shfl_xor_sync(FULLMASK, v, m);
}

// Layout: HALF-WARP per batch element, 16 amplitudes per lane.
// Within a half-warp, sub-lane sl = lane & 15 (4 bits), register r (4 bits).
// Amplitude index i = (sl << 4) | r.  Qubit q corresponds to index bit 7-q:
//   q0..q3 -> sl bits 3..0 ;  q4..q7 -> reg bits 3..0.
// All shuffle masks are <= 8, so shuffles never cross half-warp boundaries.

// ======================= REAL encoding-phase gates =======================
template<int LB>
__device__ __forceinline__ void ryl(float a[16], float c, float s, int lane) {
    const float sg = ((lane >> LB) & 1) ? s : -s;
#pragma unroll
    for (int r = 0; r < 16; ++r) {
        float p = shx(a[r], 1 << LB);
        a[r] = fmaf(sg, p, c * a[r]);
    }
}

template<int BT>
__device__ __forceinline__ void ryr(float a[16], float c, float s) {
#pragma unroll
    for (int r = 0; r < 16; ++r) {
        if (!(r & (1 << BT))) {
            const int r1 = r | (1 << BT);
            float a0 = a[r], a1 = a[r1];
            a[r]  = c * a0 - s * a1;
            a[r1] = fmaf(s, a0, c * a1);
        }
    }
}

template<int LC, int LT>
__device__ __forceinline__ void cll(float a[16], int lane) {
    const bool p = (lane >> LC) & 1;
#pragma unroll
    for (int r = 0; r < 16; ++r) {
        float q = shx(a[r], 1 << LT);
        a[r] = p ? q : a[r];
    }
}

template<int LC, int BT>
__device__ __forceinline__ void clr(float a[16], int lane) {
    const bool p = (lane >> LC) & 1;
#pragma unroll
    for (int r = 0; r < 16; ++r) {
        if (!(r & (1 << BT))) {
            const int r1 = r | (1 << BT);
            float t0 = a[r], t1 = a[r1];
            a[r]  = p ? t1 : t0;
            a[r1] = p ? t0 : t1;
        }
    }
}

template<int BC, int BT>
__device__ __forceinline__ void crr_perm(float a[16]) {
#pragma unroll
    for (int r = 0; r < 16; ++r) {
        if ((r & (1 << BC)) && !(r & (1 << BT))) {
            const int r1 = r | (1 << BT);
            float t = a[r]; a[r] = a[r1]; a[r1] = t;   // register rename after unroll
        }
    }
}

template<int BC, int LT>
__device__ __forceinline__ void crl(float a[16]) {
#pragma unroll
    for (int r = 0; r < 16; ++r) {
        if (r & (1 << BC)) a[r] = shx(a[r], 1 << LT);
    }
}

// ======================= COMPLEX final-stage gates =======================
// CRX on control==1 subspace: [[c, -i s],[-i s, c]]
template<int LC, int LT>
__device__ __forceinline__ void crx_ll(float ar[16], float ai[16], float c, float s, int lane) {
    const bool p = (lane >> LC) & 1;
    const float ce = p ? c : 1.0f;
    const float se = p ? s : 0.0f;
#pragma unroll
    for (int r = 0; r < 16; ++r) {
        float pr = shx(ar[r], 1 << LT);
        float pi = shx(ai[r], 1 << LT);
        float nr = fmaf( se, pi, ce * ar[r]);
        float ni = fmaf(-se, pr, ce * ai[r]);
        ar[r] = nr; ai[r] = ni;
    }
}

template<int LC, int BT>
__device__ __forceinline__ void crx_lr(float ar[16], float ai[16], float c, float s, int lane) {
    const bool p = (lane >> LC) & 1;
    const float ce = p ? c : 1.0f;
    const float se = p ? s : 0.0f;
#pragma unroll
    for (int r = 0; r < 16; ++r) {
        if (!(r & (1 << BT))) {
            const int r1 = r | (1 << BT);
            float a0r = ar[r], a0i = ai[r], a1r = ar[r1], a1i = ai[r1];
            ar[r]  = fmaf( se, a1i, ce * a0r);
            ai[r]  = fmaf(-se, a1r, ce * a0i);
            ar[r1] = fmaf( se, a0i, ce * a1r);
            ai[r1] = fmaf(-se, a0r, ce * a1i);
        }
    }
}

template<int BC, int BT>
__device__ __forceinline__ void crx_rr(float ar[16], float ai[16], float c, float s) {
#pragma unroll
    for (int r = 0; r < 16; ++r) {
        if ((r & (1 << BC)) && !(r & (1 << BT))) {
            const int r1 = r | (1 << BT);
            float a0r = ar[r], a0i = ai[r], a1r = ar[r1], a1i = ai[r1];
            ar[r]  = fmaf( s, a1i, c * a0r);
            ai[r]  = fmaf(-s, a1r, c * a0i);
            ar[r1] = fmaf( s, a0i, c * a1r);
            ai[r1] = fmaf(-s, a0r, c * a1i);
        }
    }
}

// Joint application of CRX(q4,q5)=(reg bit3 -> reg bit2) and CRX(q6,q7)=(reg bit1 -> reg bit0)
// to a REAL state, producing the complex state directly (no shuffles).
//   re = c^2 a[r] - s^2 a[r^5]          (both controls set)
//   im = -c s (a[r^4] + a[r^1])
__device__ __forceinline__ void crx_rr2_r2c(float ar[16], float ai[16], float c, float s) {
    float o[16];
#pragma unroll
    for (int r = 0; r < 16; ++r) o[r] = ar[r];
    const float c2 = c * c, s2 = s * s, cs = c * s;
#pragma unroll
    for (int r = 0; r < 16; ++r) {
        const bool g1 = (r & 8) != 0;   // control q4 (reg bit 3)
        const bool g2 = (r & 2) != 0;   // control q6 (reg bit 1)
        if (g1 && g2) {
            ar[r] = c2 * o[r] - s2 * o[r ^ 5];
            ai[r] = -cs * (o[r ^ 4] + o[r ^ 1]);
        } else if (g1) {
            ar[r] = c * o[r];
            ai[r] = -s * o[r ^ 4];
        } else if (g2) {
            ar[r] = c * o[r];
            ai[r] = -s * o[r ^ 1];
        } else {
            ai[r] = 0.0f;
        }
    }
}

template<int BT>
__device__ __forceinline__ void u3_reg(float ar[16], float ai[16],
    float u00r, float u00i, float u01r, float u01i,
    float u10r, float u10i, float u11r, float u11i) {
#pragma unroll
    for (int r = 0; r < 16; ++r) {
        if (!(r & (1 << BT))) {
            const int r1 = r | (1 << BT);
            float a0r = ar[r], a0i = ai[r], a1r = ar[r1], a1i = ai[r1];
            ar[r]  = u00r*a0r - u00i*a0i + u01r*a1r - u01i*a1i;
            ai[r]  = u00r*a0i + u00i*a0r + u01r*a1i + u01i*a1r;
            ar[r1] = u10r*a0r - u10i*a0i + u11r*a1r - u11i*a1i;
            ai[r1] = u10r*a0i + u10i*a0r + u11r*a1i + u11i*a1r;
        }
    }
}

template<int LT>
__device__ __forceinline__ void u3_lane(float ar[16], float ai[16],
    float u00r, float u00i, float u01r, float u01i,
    float u10r, float u10i, float u11r, float u11i, int lane) {
    const bool p = (lane >> LT) & 1;
    const float cor = p ? u11r : u00r, coi = p ? u11i : u00i;
    const float cpr = p ? u10r : u01r, cpi = p ? u10i : u01i;
#pragma unroll
    for (int r = 0; r < 16; ++r) {
        float pr = shx(ar[r], 1 << LT);
        float pi = shx(ai[r], 1 << LT);
        float vr = ar[r], vi = ai[r];
        ar[r] = cor*vr - coi*vi + cpr*pr - cpi*pi;
        ai[r] = cor*vi + coi*vr + cpr*pi + cpi*pr;
    }
}

__device__ __forceinline__ void u3_coeffs(const float* __restrict__ p3,
    float& u00r, float& u00i, float& u01r, float& u01i,
    float& u10r, float& u10i, float& u11r, float& u11i) {
    const float th = p3[0], ph = p3[1], lm = p3[2];
    float st, ct;   __sincosf(0.5f * th, &st, &ct);
    float sl, cl;   __sincosf(lm, &sl, &cl);
    float sp, cp;   __sincosf(ph, &sp, &cp);
    float spl, cpl; __sincosf(ph + lm, &spl, &cpl);
    u00r = ct;        u00i = 0.0f;
    u01r = -cl * st;  u01i = -sl * st;
    u10r =  cp * st;  u10i =  sp * st;
    u11r = cpl * ct;  u11i = spl * ct;
}

// ==================================================================================
__global__ void __launch_bounds__(256) qcnn_kernel(
    const float* __restrict__ x,
    const float* __restrict__ crx_theta,
    const float* __restrict__ u3p,
    const float* __restrict__ w1,
    const float* __restrict__ b1,
    const float* __restrict__ w2,
    const float* __restrict__ b2,
    float* __restrict__ out, int nB)
{
    const int warp = (blockIdx.x * blockDim.x + threadIdx.x) >> 5;
    if (2 * warp >= nB) return;
    const int lane = threadIdx.x & 31;
    const int hl = lane >> 4;              // element slot within warp
    const int e  = 2 * warp + hl;
    const int el = (e < nB) ? e : (nB - 1);

    // ---- per-element RY angles (reused across all 4 cycles) ----
    float c8[8], s8[8];
    {
        const float4 x0 = reinterpret_cast<const float4*>(x + el * 8)[0];
        const float4 x1 = reinterpret_cast<const float4*>(x + el * 8)[1];
        float xs[8] = {x0.x, x0.y, x0.z, x0.w, x1.x, x1.y, x1.z, x1.w};
#pragma unroll
        for (int q = 0; q < 8; ++q) __sincosf(0.5f * xs[q], &s8[q], &c8[q]);
    }

    // ---- init |0...0>, REAL state only ----
    float ar[16];
#pragma unroll
    for (int r = 0; r < 16; ++r) ar[r] = 0.0f;
    if ((lane & 15) == 0) ar[0] = 1.0f;

    // ---- 4 cycles of RY(q0..q7) then ring CNOT(q, q+1 mod 8), all real ----
#pragma unroll 1
    for (int cyc = 0; cyc < 4; ++cyc) {
        ryl<3>(ar, c8[0], s8[0], lane);    // q0
        ryl<2>(ar, c8[1], s8[1], lane);    // q1
        ryl<1>(ar, c8[2], s8[2], lane);    // q2
        ryl<0>(ar, c8[3], s8[3], lane);    // q3
        ryr<3>(ar, c8[4], s8[4]);          // q4
        ryr<2>(ar, c8[5], s8[5]);          // q5
        ryr<1>(ar, c8[6], s8[6]);          // q6
        ryr<0>(ar, c8[7], s8[7]);          // q7

        cll<3, 2>(ar, lane);               // (q0,q1)
        cll<2, 1>(ar, lane);               // (q1,q2)
        cll<1, 0>(ar, lane);               // (q2,q3)
        clr<0, 3>(ar, lane);               // (q3,q4)
        crr_perm<3, 2>(ar);                // (q4,q5)
        crr_perm<2, 1>(ar);                // (q5,q6)
        crr_perm<1, 0>(ar);                // (q6,q7)
        crl<0, 3>(ar);                     // (q7,q0)
    }

    float ai[16];

    // ---- layer 0: CRX(theta0) on pairs (0,1)(2,3)(4,5)(6,7) then (1,2)(3,4)(5,6) ----
    {
        float s0, c0;
        __sincosf(0.5f * crx_theta[0], &s0, &c0);
        // even pairs commute: do the two register-pair gates jointly from the real state
        crx_rr2_r2c(ar, ai, c0, s0);              // (q4,q5) and (q6,q7), real->complex
        crx_ll<3, 2>(ar, ai, c0, s0, lane);       // (q0,q1)
        crx_ll<1, 0>(ar, ai, c0, s0, lane);       // (q2,q3)
        // odd pairs
        crx_ll<2, 1>(ar, ai, c0, s0, lane);       // (q1,q2)
        crx_lr<0, 3>(ar, ai, c0, s0, lane);       // (q3,q4)
        crx_rr<2, 1>(ar, ai, c0, s0);             // (q5,q6)
    }
    // ---- layer 0: U3 on qubits [1,3,5,7] ----
    {
        float u00r,u00i,u01r,u01i,u10r,u10i,u11r,u11i;
        u3_coeffs(u3p, u00r,u00i,u01r,u01i,u10r,u10i,u11r,u11i);
        u3_lane<2>(ar, ai, u00r,u00i,u01r,u01i,u10r,u10i,u11r,u11i, lane); // q1
        u3_lane<0>(ar, ai, u00r,u00i,u01r,u01i,u10r,u10i,u11r,u11i, lane); // q3
        u3_reg<2>(ar, ai, u00r,u00i,u01r,u01i,u10r,u10i,u11r,u11i);        // q5
        u3_reg<0>(ar, ai, u00r,u00i,u01r,u01i,u10r,u10i,u11r,u11i);        // q7
    }
    // ---- layer 1: CRX(theta1) on active [1,3,5,7]: (1,3)(5,7) then (3,5) ----
    {
        float s1, c1;
        __sincosf(0.5f * crx_theta[1], &s1, &c1);
        crx_ll<2, 0>(ar, ai, c1, s1, lane);       // (q1,q3)
        crx_rr<2, 0>(ar, ai, c1, s1);             // (q5,q7)
        crx_lr<0, 2>(ar, ai, c1, s1, lane);       // (q3,q5)
    }
    // ---- layer 1: U3 on qubits [3,7] ----
    {
        float u00r,u00i,u01r,u01i,u10r,u10i,u11r,u11i;
        u3_coeffs(u3p + 3, u00r,u00i,u01r,u01i,u10r,u10i,u11r,u11i);
        u3_lane<0>(ar, ai, u00r,u00i,u01r,u01i,u10r,u10i,u11r,u11i, lane); // q3
        u3_reg<0>(ar, ai, u00r,u00i,u01r,u01i,u10r,u10i,u11r,u11i);        // q7
    }

    // ---- expectation values: f0 = <Z_q3> (lane bit 0), f1 = <Z_q7> (reg bit 0) ----
    float sAll = 0.0f, sB = 0.0f;
#pragma unroll
    for (int r = 0; r < 16; ++r) {
        float m2 = ar[r] * ar[r] + ai[r] * ai[r];
        sAll += m2;
        sB += (r & 1) ? -m2 : m2;
    }
    float f0 = (lane & 1) ? -sAll : sAll;
    float f1 = sB;
#pragma unroll
    for (int m = 8; m >= 1; m >>= 1) {   // stays within half-warp
        f0 += shx(f0, m);
        f1 += shx(f1, m);
    }

    // ---- MLP head: sigmoid(tanh(f @ w1 + b1) @ w2 + b2), tanh spread over 10 lanes ----
    const int sl = lane & 15;
    float contrib = 0.0f;
    if (sl < 10) {
        float h = tanhf(fmaf(f0, w1[sl], fmaf(f1, w1[10 + sl], b1[sl])));
        contrib = h * w2[sl];
    }
#pragma unroll
    for (int m = 8; m >= 1; m >>= 1) contrib += shx(contrib, m);
    if (sl == 0 && e < nB) {
        out[e] = 1.0f / (1.0f + __expf(-(contrib + b2[0])));
    }
}

extern "C" void kernel_launch(void* const* d_in, const int* in_sizes, int n_in,
                              void* d_out, int out_size) {
    const float* x         = (const float*)d_in[0];
    const float* crx_theta = (const float*)d_in[1];
    const float* u3_params = (const float*)d_in[2];
    const float* w1        = (const float*)d_in[3];
    const float* b1        = (const float*)d_in[4];
    const float* w2        = (const float*)d_in[5];
    const float* b2        = (const float*)d_in[6];
    float* out = (float*)d_out;

    const int nB = out_size;                  // (B, 1) output -> B batch elements
    const int threads = 256;                  // 8 warps/block, 2 elements per warp
    const int nWarps = (nB + 1) / 2;
    const int blocks = (nWarps * 32 + threads - 1) / threads;
    qcnn_kernel<<<blocks, threads>>>(x, crx_theta, u3_params, w1, b1, w2, b2, out, nB);
}

// round 3
// speedup vs baseline: 2.3682x; 1.2759x over previous
#include <cuda_runtime.h>

#define FULLMASK 0xffffffffu

__device__ __forceinline__ float shx(float v, int m) { return __shfl_xor_sync(FULLMASK, v, m); }

// Packed fp32x2 math (Blackwell FFMA2 path — only reachable via PTX f32x2)
__device__ __forceinline__ void mul2(float& d0, float& d1, float a0, float a1,
                                     float b0, float b1) {
    asm("{\n\t.reg .b64 A,B,D;\n\t"
        "mov.b64 A, {%2,%3};\n\t"
        "mov.b64 B, {%4,%5};\n\t"
        "mul.rn.f32x2 D, A, B;\n\t"
        "mov.b64 {%0,%1}, D;\n\t}"
        : "=f"(d0), "=f"(d1) : "f"(a0), "f"(a1), "f"(b0), "f"(b1));
}
__device__ __forceinline__ void fma2(float& d0, float& d1, float a0, float a1,
                                     float b0, float b1, float c0, float c1) {
    asm("{\n\t.reg .b64 A,B,C,D;\n\t"
        "mov.b64 A, {%2,%3};\n\t"
        "mov.b64 B, {%4,%5};\n\t"
        "mov.b64 C, {%6,%7};\n\t"
        "fma.rn.f32x2 D, A, B, C;\n\t"
        "mov.b64 {%0,%1}, D;\n\t}"
        : "=f"(d0), "=f"(d1) : "f"(a0), "f"(a1), "f"(b0), "f"(b1), "f"(c0), "f"(c1));
}

// Layout: HALF-WARP per batch element, 16 amplitudes per lane.
// sub-lane sl = lane & 15 (bits L3..L0), register index r (bits R3..R0).
// Qubit -> bit mapping (parity trick: odd qubits live in registers):
//   q0->L3  q2->L2  q4->L1  q6->L0     (lane bits)
//   q1->R3  q3->R2  q5->R1  q7->R0     (register bits)
// All shuffle masks <= 8 => shuffles never cross the half-warp boundary.

// ---------------- RY on a lane bit (f32x2) ----------------
template<int LB>
__device__ __forceinline__ void ryl2(float a[16], float c, float s, int lane) {
    const float sg = ((lane >> LB) & 1) ? s : -s;
#pragma unroll
    for (int r = 0; r < 16; r += 2) {
        float p0 = shx(a[r],     1 << LB);
        float p1 = shx(a[r + 1], 1 << LB);
        float t0, t1;
        mul2(t0, t1, a[r], a[r + 1], c, c);
        fma2(t0, t1, p0, p1, sg, sg, t0, t1);
        a[r] = t0; a[r + 1] = t1;
    }
}

// RY on lane bit LB fused with a pending CNOT(control = reg bit 0, target = lane bit LB).
// For regs with control bit set (odd r), the CNOT pre-swaps own/partner:
//   new = c*partner + sg*own  (vs normal new = c*own + sg*partner)
template<int LB>
__device__ __forceinline__ void ryl2_cx(float a[16], float c, float s, int lane) {
    const float sg = ((lane >> LB) & 1) ? s : -s;
#pragma unroll
    for (int r = 0; r < 16; r += 2) {
        float p0 = shx(a[r],     1 << LB);   // r even: control clear
        float p1 = shx(a[r + 1], 1 << LB);   // r+1 odd: control set
        float t0, t1;
        mul2(t0, t1, a[r], p1, c, c);
        fma2(t0, t1, p0, a[r + 1], sg, sg, t0, t1);
        a[r] = t0; a[r + 1] = t1;
    }
}

// ---------------- RY on a reg bit (f32x2, two butterflies per vector op) ----------------
template<int BT>
__device__ __forceinline__ void ryr2(float a[16], float c, float s) {
#pragma unroll
    for (int j = 0; j < 4; ++j) {
        const int k0 = 2 * j, k1 = 2 * j + 1;
        const int p = ((k0 >> BT) << (BT + 1)) | (k0 & ((1 << BT) - 1));
        const int q = ((k1 >> BT) << (BT + 1)) | (k1 & ((1 << BT) - 1));
        const int pm = p | (1 << BT), qm = q | (1 << BT);
        float l0, l1, h0, h1;
        mul2(l0, l1, a[p], a[q], c, c);                    // c*L
        mul2(h0, h1, a[p], a[q], s, s);                    // s*L
        fma2(l0, l1, a[pm], a[qm], -s, -s, l0, l1);        // c*L - s*H
        fma2(h0, h1, a[pm], a[qm],  c,  c, h0, h1);        // s*L + c*H
        a[p] = l0; a[q] = l1; a[pm] = h0; a[qm] = h1;
    }
}

// ---------------- CNOT: control lane bit LC, target reg bit BT (selects only) ----------------
template<int LC, int BT>
__device__ __forceinline__ void clr(float a[16], int lane) {
    const bool p = (lane >> LC) & 1;
#pragma unroll
    for (int r = 0; r < 16; ++r) {
        if (!(r & (1 << BT))) {
            const int r1 = r | (1 << BT);
            float t0 = a[r], t1 = a[r1];
            a[r]  = p ? t1 : t0;
            a[r1] = p ? t0 : t1;
        }
    }
}

// ---------------- CNOT: control reg bit BC, target lane bit LT (8 shuffles) ----------------
template<int BC, int LT>
__device__ __forceinline__ void crl(float a[16]) {
#pragma unroll
    for (int r = 0; r < 16; ++r) {
        if (r & (1 << BC)) a[r] = shx(a[r], 1 << LT);
    }
}

// ---------------- CRX gates: [[c, -i s],[-i s, c]] on control==1 subspace ----------------
// real -> complex version (state imaginary part identically 0 on input)
template<int LC, int BT>
__device__ __forceinline__ void crx_lr_r2c(float ar[16], float ai[16], float c, float s, int lane) {
    const bool p = (lane >> LC) & 1;
    const float ce  = p ? c   : 1.0f;
    const float nse = p ? -s  : 0.0f;
#pragma unroll
    for (int r = 0; r < 16; ++r) {
        if (!(r & (1 << BT))) {
            const int r1 = r | (1 << BT);
            ai[r]  = nse * ar[r1];
            ai[r1] = nse * ar[r];
            ar[r]  = ce * ar[r];
            ar[r1] = ce * ar[r1];
        }
    }
}

// complex, control lane / target reg (no shuffles)
template<int LC, int BT>
__device__ __forceinline__ void crx_lr(float ar[16], float ai[16], float c, float s, int lane) {
    const bool p = (lane >> LC) & 1;
    const float ce = p ? c : 1.0f;
    const float se = p ? s : 0.0f;
#pragma unroll
    for (int r = 0; r < 16; ++r) {
        if (!(r & (1 << BT))) {
            const int r1 = r | (1 << BT);
            float a0r = ar[r], a0i = ai[r], a1r = ar[r1], a1i = ai[r1];
            ar[r]  = fmaf( se, a1i, ce * a0r);
            ai[r]  = fmaf(-se, a1r, ce * a0i);
            ar[r1] = fmaf( se, a0i, ce * a1r);
            ai[r1] = fmaf(-se, a0r, ce * a1i);
        }
    }
}

// complex, control reg / target lane (16 shuffles; matrix symmetric so both partners identical)
template<int BC, int LT>
__device__ __forceinline__ void crx_rl(float ar[16], float ai[16], float c, float s) {
#pragma unroll
    for (int r = 0; r < 16; ++r) {
        if (r & (1 << BC)) {
            float pr = shx(ar[r], 1 << LT);
            float pi = shx(ai[r], 1 << LT);
            float nr = fmaf( s, pi, c * ar[r]);
            float ni = fmaf(-s, pr, c * ai[r]);
            ar[r] = nr; ai[r] = ni;
        }
    }
}

// complex, both bits in registers (no shuffles)
template<int BC, int BT>
__device__ __forceinline__ void crx_rr(float ar[16], float ai[16], float c, float s) {
#pragma unroll
    for (int r = 0; r < 16; ++r) {
        if ((r & (1 << BC)) && !(r & (1 << BT))) {
            const int r1 = r | (1 << BT);
            float a0r = ar[r], a0i = ai[r], a1r = ar[r1], a1i = ai[r1];
            ar[r]  = fmaf( s, a1i, c * a0r);
            ai[r]  = fmaf(-s, a1r, c * a0i);
            ar[r1] = fmaf( s, a0i, c * a1r);
            ai[r1] = fmaf(-s, a0r, c * a1i);
        }
    }
}

// ---------------- U3 on a reg bit (no shuffles) ----------------
template<int BT>
__device__ __forceinline__ void u3_reg(float ar[16], float ai[16],
    float u00r, float u00i, float u01r, float u01i,
    float u10r, float u10i, float u11r, float u11i) {
#pragma unroll
    for (int r = 0; r < 16; ++r) {
        if (!(r & (1 << BT))) {
            const int r1 = r | (1 << BT);
            float a0r = ar[r], a0i = ai[r], a1r = ar[r1], a1i = ai[r1];
            ar[r]  = u00r*a0r - u00i*a0i + u01r*a1r - u01i*a1i;
            ai[r]  = u00r*a0i + u00i*a0r + u01r*a1i + u01i*a1r;
            ar[r1] = u10r*a0r - u10i*a0i + u11r*a1r - u11i*a1i;
            ai[r1] = u10r*a0i + u10i*a0r + u11r*a1i + u11i*a1r;
        }
    }
}

__device__ __forceinline__ void u3_coeffs(const float* __restrict__ p3,
    float& u00r, float& u00i, float& u01r, float& u01i,
    float& u10r, float& u10i, float& u11r, float& u11i) {
    const float th = p3[0], ph = p3[1], lm = p3[2];
    float st, ct;   __sincosf(0.5f * th, &st, &ct);
    float sl, cl;   __sincosf(lm, &sl, &cl);
    float sp, cp;   __sincosf(ph, &sp, &cp);
    float spl, cpl; __sincosf(ph + lm, &spl, &cpl);
    u00r = ct;        u00i = 0.0f;
    u01r = -cl * st;  u01i = -sl * st;
    u10r =  cp * st;  u10i =  sp * st;
    u11r = cpl * ct;  u11i = spl * ct;
}

// CNOT ring layer, trailing CNOT(q7,q0) deferred (fused into next RY or applied explicitly)
__device__ __forceinline__ void cnot_layer(float a[16], int lane) {
    clr<3, 3>(a, lane);   // (q0,q1)
    crl<3, 2>(a);         // (q1,q2)
    clr<2, 2>(a, lane);   // (q2,q3)
    crl<2, 1>(a);         // (q3,q4)
    clr<1, 1>(a, lane);   // (q4,q5)
    crl<1, 0>(a);         // (q5,q6)
    clr<0, 0>(a, lane);   // (q6,q7)
}

// ==================================================================================
__global__ void __launch_bounds__(256) qcnn_kernel(
    const float* __restrict__ x,
    const float* __restrict__ crx_theta,
    const float* __restrict__ u3p,
    const float* __restrict__ w1,
    const float* __restrict__ b1,
    const float* __restrict__ w2,
    const float* __restrict__ b2,
    float* __restrict__ out, int nB)
{
    const int warp = (blockIdx.x * blockDim.x + threadIdx.x) >> 5;
    if (2 * warp >= nB) return;
    const int lane = threadIdx.x & 31;
    const int hl = lane >> 4;
    const int e  = 2 * warp + hl;
    const int el = (e < nB) ? e : (nB - 1);
    const int sl = lane & 15;

    // ---- per-element RY angles (reused across all 4 cycles) ----
    float c8[8], s8[8];
    {
        const float4 x0 = reinterpret_cast<const float4*>(x + el * 8)[0];
        const float4 x1 = reinterpret_cast<const float4*>(x + el * 8)[1];
        float xs[8] = {x0.x, x0.y, x0.z, x0.w, x1.x, x1.y, x1.z, x1.w};
#pragma unroll
        for (int q = 0; q < 8; ++q) __sincosf(0.5f * xs[q], &s8[q], &c8[q]);
    }

    // ---- cycle 1 RY layer applied to |0..0> == product state, built directly ----
    float a[16];
    {
        float laneF = ((sl & 8) ? s8[0] : c8[0]) * ((sl & 4) ? s8[2] : c8[2]);
        laneF *= ((sl & 2) ? s8[4] : c8[4]) * ((sl & 1) ? s8[6] : c8[6]);
        // reg bits: R3=q1, R2=q3, R1=q5, R0=q7
        float t0 = laneF * c8[1], t1 = laneF * s8[1];
        float u0 = t0 * c8[3], u1 = t0 * s8[3], u2 = t1 * c8[3], u3 = t1 * s8[3];
        float v[8];
        v[0] = u0 * c8[5]; v[1] = u0 * s8[5]; v[2] = u1 * c8[5]; v[3] = u1 * s8[5];
        v[4] = u2 * c8[5]; v[5] = u2 * s8[5]; v[6] = u3 * c8[5]; v[7] = u3 * s8[5];
#pragma unroll
        for (int j = 0; j < 8; ++j) {
            a[2 * j]     = v[j] * c8[7];
            a[2 * j + 1] = v[j] * s8[7];
        }
    }

    // ---- cycle 1 CNOT ring (trailing (q7,q0) deferred) ----
    cnot_layer(a, lane);

    // ---- cycles 2..4: RY layer (RY(q0) fused with pending CNOT(q7,q0)) + CNOT ring ----
#pragma unroll 1
    for (int cyc = 0; cyc < 3; ++cyc) {
        ryl2_cx<3>(a, c8[0], s8[0], lane);   // CNOT(q7,q0) + RY(q0)
        ryr2<3>(a, c8[1], s8[1]);            // RY(q1)
        ryl2<2>(a, c8[2], s8[2], lane);      // RY(q2)
        ryr2<2>(a, c8[3], s8[3]);            // RY(q3)
        ryl2<1>(a, c8[4], s8[4], lane);      // RY(q4)
        ryr2<1>(a, c8[5], s8[5]);            // RY(q5)
        ryl2<0>(a, c8[6], s8[6], lane);      // RY(q6)
        ryr2<0>(a, c8[7], s8[7]);            // RY(q7)
        cnot_layer(a, lane);
    }
    crl<0, 3>(a);                            // final pending CNOT(q7,q0)

    // ================= final (complex) stage =================
    float* ar = a;
    float ai[16];

    // ---- layer 0 CRX: even pairs (0,1)(2,3)(4,5)(6,7), then odd (1,2)(3,4)(5,6) ----
    {
        float s0, c0;
        __sincosf(0.5f * crx_theta[0], &s0, &c0);
        crx_lr_r2c<3, 3>(ar, ai, c0, s0, lane);  // (q0,q1): real -> complex
        crx_lr<2, 2>(ar, ai, c0, s0, lane);      // (q2,q3)
        crx_lr<1, 1>(ar, ai, c0, s0, lane);      // (q4,q5)
        crx_lr<0, 0>(ar, ai, c0, s0, lane);      // (q6,q7)
        crx_rl<3, 2>(ar, ai, c0, s0);            // (q1,q2)
        crx_rl<2, 1>(ar, ai, c0, s0);            // (q3,q4)
        crx_rl<1, 0>(ar, ai, c0, s0);            // (q5,q6)
    }
    // ---- layer 0 U3 on qubits [1,3,5,7] (all register-local) ----
    {
        float u00r,u00i,u01r,u01i,u10r,u10i,u11r,u11i;
        u3_coeffs(u3p, u00r,u00i,u01r,u01i,u10r,u10i,u11r,u11i);
        u3_reg<3>(ar, ai, u00r,u00i,u01r,u01i,u10r,u10i,u11r,u11i);  // q1
        u3_reg<2>(ar, ai, u00r,u00i,u01r,u01i,u10r,u10i,u11r,u11i);  // q3
        u3_reg<1>(ar, ai, u00r,u00i,u01r,u01i,u10r,u10i,u11r,u11i);  // q5
        u3_reg<0>(ar, ai, u00r,u00i,u01r,u01i,u10r,u10i,u11r,u11i);  // q7
    }
    // ---- layer 1 CRX on [1,3,5,7]: (1,3)(5,7) then (3,5) — all register-local ----
    {
        float s1, c1;
        __sincosf(0.5f * crx_theta[1], &s1, &c1);
        crx_rr<3, 2>(ar, ai, c1, s1);    // (q1,q3)
        crx_rr<1, 0>(ar, ai, c1, s1);    // (q5,q7)
        crx_rr<2, 1>(ar, ai, c1, s1);    // (q3,q5)
    }
    // ---- layer 1 U3 on qubits [3,7] — register-local ----
    {
        float u00r,u00i,u01r,u01i,u10r,u10i,u11r,u11i;
        u3_coeffs(u3p + 3, u00r,u00i,u01r,u01i,u10r,u10i,u11r,u11i);
        u3_reg<2>(ar, ai, u00r,u00i,u01r,u01i,u10r,u10i,u11r,u11i);  // q3
        u3_reg<0>(ar, ai, u00r,u00i,u01r,u01i,u10r,u10i,u11r,u11i);  // q7
    }

    // ---- expvals: f0 = <Z_q3> (reg bit 2), f1 = <Z_q7> (reg bit 0) ----
    float bk[4] = {0.0f, 0.0f, 0.0f, 0.0f};
#pragma unroll
    for (int r = 0; r < 16; ++r) {
        float m2 = fmaf(ar[r], ar[r], ai[r] * ai[r]);
        bk[(((r >> 2) & 1) << 1) | (r & 1)] += m2;
    }
    float f0 = (bk[0] + bk[1]) - (bk[2] + bk[3]);
    float f1 = (bk[0] + bk[2]) - (bk[1] + bk[3]);
#pragma unroll
    for (int m = 8; m >= 1; m >>= 1) {   // stays within half-warp
        f0 += shx(f0, m);
        f1 += shx(f1, m);
    }

    // ---- MLP head: sigmoid(tanh(f @ w1 + b1) @ w2 + b2), tanh spread over 10 lanes ----
    float contrib = 0.0f;
    if (sl < 10) {
        float h = tanhf(fmaf(f0, w1[sl], fmaf(f1, w1[10 + sl], b1[sl])));
        contrib = h * w2[sl];
    }
#pragma unroll
    for (int m = 8; m >= 1; m >>= 1) contrib += shx(contrib, m);
    if (sl == 0 && e < nB) {
        out[e] = 1.0f / (1.0f + __expf(-(contrib + b2[0])));
    }
}

extern "C" void kernel_launch(void* const* d_in, const int* in_sizes, int n_in,
                              void* d_out, int out_size) {
    const float* x         = (const float*)d_in[0];
    const float* crx_theta = (const float*)d_in[1];
    const float* u3_params = (const float*)d_in[2];
    const float* w1        = (const float*)d_in[3];
    const float* b1        = (const float*)d_in[4];
    const float* w2        = (const float*)d_in[5];
    const float* b2        = (const float*)d_in[6];
    float* out = (float*)d_out;

    const int nB = out_size;                  // (B, 1) output -> B batch elements
    const int threads = 256;                  // 8 warps/block, 2 elements per warp
    const int nWarps = (nB + 1) / 2;
    const int blocks = (nWarps * 32 + threads - 1) / threads;
    qcnn_kernel<<<blocks, threads>>>(x, crx_theta, u3_params, w1, b1, w2, b2, out, nB);
}

// round 5
// speedup vs baseline: 2.8223x; 1.1918x over previous
#include <cuda_runtime.h>

#define FULLMASK 0xffffffffu

__device__ __forceinline__ float shx(float v, int m) { return __shfl_xor_sync(FULLMASK, v, m); }

// Packed fp32x2 math (Blackwell FFMA2 path — only reachable via PTX f32x2)
__device__ __forceinline__ void mul2(float& d0, float& d1, float a0, float a1,
                                     float b0, float b1) {
    asm("{\n\t.reg .b64 A,B,D;\n\t"
        "mov.b64 A, {%2,%3};\n\t"
        "mov.b64 B, {%4,%5};\n\t"
        "mul.rn.f32x2 D, A, B;\n\t"
        "mov.b64 {%0,%1}, D;\n\t}"
        : "=f"(d0), "=f"(d1) : "f"(a0), "f"(a1), "f"(b0), "f"(b1));
}
__device__ __forceinline__ void fma2(float& d0, float& d1, float a0, float a1,
                                     float b0, float b1, float c0, float c1) {
    asm("{\n\t.reg .b64 A,B,C,D;\n\t"
        "mov.b64 A, {%2,%3};\n\t"
        "mov.b64 B, {%4,%5};\n\t"
        "mov.b64 C, {%6,%7};\n\t"
        "fma.rn.f32x2 D, A, B, C;\n\t"
        "mov.b64 {%0,%1}, D;\n\t}"
        : "=f"(d0), "=f"(d1) : "f"(a0), "f"(a1), "f"(b0), "f"(b1), "f"(c0), "f"(c1));
}

// Layout: HALF-WARP per batch element, 16 amplitudes per lane.
// sub-lane sl = lane & 15 (bits L3..L0), register index r (bits R3..R0).
// Qubit -> bit mapping (parity trick: odd qubits live in registers):
//   q0->L3  q2->L2  q4->L1  q6->L0     (lane bits)
//   q1->R3  q3->R2  q5->R1  q7->R0     (register bits)
// All shuffle masks <= 8 => shuffles never cross the half-warp boundary.

// ---- RY on lane bit LB with PRE-CNOT(control = reg bit 0) fused (ring-closing CX(7,0)) ----
template<int LB>
__device__ __forceinline__ void ryl2_cx(float a[16], float c, float s, int lane) {
    const float sg = ((lane >> LB) & 1) ? s : -s;
#pragma unroll
    for (int r = 0; r < 16; r += 2) {
        float p0 = shx(a[r],     1 << LB);   // r even: control clear
        float p1 = shx(a[r + 1], 1 << LB);   // r+1 odd: control set -> pre-swap own/partner
        float t0, t1;
        mul2(t0, t1, a[r], p1, c, c);
        fma2(t0, t1, p0, a[r + 1], sg, sg, t0, t1);
        a[r] = t0; a[r + 1] = t1;
    }
}

// ---- RY on lane bit LB with POST-CNOT(control = reg bit CB, target = same lane bit) fused ----
// uncontrolled regs: new = c*v + sg*p ; controlled regs: new = c*p - sg*v   (zero extra cost)
template<int LB, int CB>
__device__ __forceinline__ void ryl2_post(float a[16], float c, float s, int lane) {
    const float sg = ((lane >> LB) & 1) ? s : -s;
    const float nsg = -sg;
#pragma unroll
    for (int r = 0; r < 16; r += 2) {
        float p0 = shx(a[r],     1 << LB);
        float p1 = shx(a[r + 1], 1 << LB);
        float t0, t1;
        if (r & (1 << CB)) {          // CB >= 1 so pair is homogeneous
            mul2(t0, t1, p0, p1, c, c);
            fma2(t0, t1, a[r], a[r + 1], nsg, nsg, t0, t1);
        } else {
            mul2(t0, t1, a[r], a[r + 1], c, c);
            fma2(t0, t1, p0, p1, sg, sg, t0, t1);
        }
        a[r] = t0; a[r + 1] = t1;
    }
}

// ---- RY on reg bit BT with POST-CNOT(control = lane bit LC, target = same reg bit) fused ----
// !ctrl: (low,high) = (cL - sH, sL + cH) ; ctrl: swapped = (sL + cH, cL - sH)
template<int BT, int LC>
__device__ __forceinline__ void ryr2_cx(float a[16], float c, float s, int lane) {
    const bool p = (lane >> LC) & 1;
    const float A = p ?  s : c;
    const float B = p ?  c : -s;
    const float C = p ?  c : s;
    const float D = p ? -s : c;
#pragma unroll
    for (int j = 0; j < 4; ++j) {
        const int k0 = 2 * j, k1 = 2 * j + 1;
        const int pp = ((k0 >> BT) << (BT + 1)) | (k0 & ((1 << BT) - 1));
        const int qq = ((k1 >> BT) << (BT + 1)) | (k1 & ((1 << BT) - 1));
        const int pm = pp | (1 << BT), qm = qq | (1 << BT);
        float l0, l1, h0, h1;
        mul2(l0, l1, a[pp], a[qq], A, A);
        fma2(l0, l1, a[pm], a[qm], B, B, l0, l1);
        mul2(h0, h1, a[pp], a[qq], C, C);
        fma2(h0, h1, a[pm], a[qm], D, D, h0, h1);
        a[pp] = l0; a[qq] = l1; a[pm] = h0; a[qm] = h1;
    }
}

// ---- CNOT: control reg bit BC, target lane bit LT (8 shuffles) ----
template<int BC, int LT>
__device__ __forceinline__ void crl(float a[16]) {
#pragma unroll
    for (int r = 0; r < 16; ++r) {
        if (r & (1 << BC)) a[r] = shx(a[r], 1 << LT);
    }
}

// ---------------- CRX gates: [[c, -i s],[-i s, c]] on control==1 subspace ----------------
template<int LC, int BT>
__device__ __forceinline__ void crx_lr_r2c(float ar[16], float ai[16], float c, float s, int lane) {
    const bool p = (lane >> LC) & 1;
    const float ce  = p ? c  : 1.0f;
    const float nse = p ? -s : 0.0f;
#pragma unroll
    for (int r = 0; r < 16; ++r) {
        if (!(r & (1 << BT))) {
            const int r1 = r | (1 << BT);
            ai[r]  = nse * ar[r1];
            ai[r1] = nse * ar[r];
            ar[r]  = ce * ar[r];
            ar[r1] = ce * ar[r1];
        }
    }
}

template<int LC, int BT>
__device__ __forceinline__ void crx_lr(float ar[16], float ai[16], float c, float s, int lane) {
    const bool p = (lane >> LC) & 1;
    const float ce = p ? c : 1.0f;
    const float se = p ? s : 0.0f;
#pragma unroll
    for (int r = 0; r < 16; ++r) {
        if (!(r & (1 << BT))) {
            const int r1 = r | (1 << BT);
            float a0r = ar[r], a0i = ai[r], a1r = ar[r1], a1i = ai[r1];
            ar[r]  = fmaf( se, a1i, ce * a0r);
            ai[r]  = fmaf(-se, a1r, ce * a0i);
            ar[r1] = fmaf( se, a0i, ce * a1r);
            ai[r1] = fmaf(-se, a0r, ce * a1i);
        }
    }
}

template<int BC, int LT>
__device__ __forceinline__ void crx_rl(float ar[16], float ai[16], float c, float s) {
#pragma unroll
    for (int r = 0; r < 16; ++r) {
        if (r & (1 << BC)) {
            float pr = shx(ar[r], 1 << LT);
            float pi = shx(ai[r], 1 << LT);
            float nr = fmaf( s, pi, c * ar[r]);
            float ni = fmaf(-s, pr, c * ai[r]);
            ar[r] = nr; ai[r] = ni;
        }
    }
}

template<int BC, int BT>
__device__ __forceinline__ void crx_rr(float ar[16], float ai[16], float c, float s) {
#pragma unroll
    for (int r = 0; r < 16; ++r) {
        if ((r & (1 << BC)) && !(r & (1 << BT))) {
            const int r1 = r | (1 << BT);
            float a0r = ar[r], a0i = ai[r], a1r = ar[r1], a1i = ai[r1];
            ar[r]  = fmaf( s, a1i, c * a0r);
            ai[r]  = fmaf(-s, a1r, c * a0i);
            ar[r1] = fmaf( s, a0i, c * a1r);
            ai[r1] = fmaf(-s, a0r, c * a1i);
        }
    }
}

// ---------------- U3 on a reg bit (no shuffles); exploits u00i == 0 ----------------
template<int BT>
__device__ __forceinline__ void u3_reg(float ar[16], float ai[16],
    float u00r, float u01r, float u01i,
    float u10r, float u10i, float u11r, float u11i) {
#pragma unroll
    for (int r = 0; r < 16; ++r) {
        if (!(r & (1 << BT))) {
            const int r1 = r | (1 << BT);
            float a0r = ar[r], a0i = ai[r], a1r = ar[r1], a1i = ai[r1];
            ar[r]  = fmaf(-u01i, a1i, fmaf(u01r, a1r, u00r * a0r));
            ai[r]  = fmaf( u01i, a1r, fmaf(u01r, a1i, u00r * a0i));
            ar[r1] = fmaf(-u11i, a1i, fmaf(u11r, a1r, fmaf(-u10i, a0i, u10r * a0r)));
            ai[r1] = fmaf( u11i, a1r, fmaf(u11r, a1i, fmaf( u10i, a0r, u10r * a0i)));
        }
    }
}

__device__ __forceinline__ void u3_coeffs(const float* __restrict__ p3,
    float& u00r, float& u01r, float& u01i,
    float& u10r, float& u10i, float& u11r, float& u11i) {
    const float th = p3[0], ph = p3[1], lm = p3[2];
    float st, ct;   __sincosf(0.5f * th, &st, &ct);
    float sl, cl;   __sincosf(lm, &sl, &cl);
    float sp, cp;   __sincosf(ph, &sp, &cp);
    float spl, cpl; __sincosf(ph + lm, &spl, &cpl);
    u00r = ct;
    u01r = -cl * st;  u01i = -sl * st;
    u10r =  cp * st;  u10i =  sp * st;
    u11r = cpl * ct;  u11i = spl * ct;
}

// ==================================================================================
__global__ void __launch_bounds__(256, 4) qcnn_kernel(
    const float* __restrict__ x,
    const float* __restrict__ crx_theta,
    const float* __restrict__ u3p,
    const float* __restrict__ w1,
    const float* __restrict__ b1,
    const float* __restrict__ w2,
    const float* __restrict__ b2,
    float* __restrict__ out, int nB)
{
    const int warp = (blockIdx.x * blockDim.x + threadIdx.x) >> 5;
    if (2 * warp >= nB) return;
    const int lane = threadIdx.x & 31;
    const int hl = lane >> 4;
    const int e  = 2 * warp + hl;
    const int el = (e < nB) ? e : (nB - 1);
    const int sl = lane & 15;

    // ---- per-element RY angles (reused across all 4 cycles) ----
    float c8[8], s8[8];
    {
        const float4 x0 = reinterpret_cast<const float4*>(x + el * 8)[0];
        const float4 x1 = reinterpret_cast<const float4*>(x + el * 8)[1];
        float xs[8] = {x0.x, x0.y, x0.z, x0.w, x1.x, x1.y, x1.z, x1.w};
#pragma unroll
        for (int q = 0; q < 8; ++q) __sincosf(0.5f * xs[q], &s8[q], &c8[q]);
    }

    // ---- cycle 1: RY layer on |0..0> followed by the CNOT ring (minus (q7,q0)),
    //      built in closed form. Ring = prefix-XOR permutation: amplitude at final
    //      index f equals prod_k (g_k ? s_k : c_k), g_0 = f_0, g_k = f_k ^ f_{k-1}.
    float a[16];
    {
        const bool L3 = sl & 8, L2 = sl & 4, L1 = sl & 2, L0 = sl & 1;
        const float P0  = L3 ? s8[0] : c8[0];
        const float w3a = (L3 ? s8[1] : c8[1]) * (L2 ? s8[2] : c8[2]);   // R3 = 0
        const float w3b = (L3 ? c8[1] : s8[1]) * (L2 ? c8[2] : s8[2]);   // R3 = 1
        const float w2a = (L2 ? s8[3] : c8[3]) * (L1 ? s8[4] : c8[4]);
        const float w2b = (L2 ? c8[3] : s8[3]) * (L1 ? c8[4] : s8[4]);
        const float w1a = (L1 ? s8[5] : c8[5]) * (L0 ? s8[6] : c8[6]);
        const float w1b = (L1 ? c8[5] : s8[5]) * (L0 ? c8[6] : s8[6]);
        const float w0a = L0 ? s8[7] : c8[7];
        const float w0b = L0 ? c8[7] : s8[7];
        const float A0 = P0 * w3a, A1 = P0 * w3b;
        const float B00 = A0 * w2a, B01 = A0 * w2b, B10 = A1 * w2a, B11 = A1 * w2b;
        const float C0 = B00 * w1a, C1 = B00 * w1b, C2 = B01 * w1a, C3 = B01 * w1b;
        const float C4 = B10 * w1a, C5 = B10 * w1b, C6 = B11 * w1a, C7 = B11 * w1b;
        a[0]  = C0 * w0a;  a[1]  = C0 * w0b;  a[2]  = C1 * w0a;  a[3]  = C1 * w0b;
        a[4]  = C2 * w0a;  a[5]  = C2 * w0b;  a[6]  = C3 * w0a;  a[7]  = C3 * w0b;
        a[8]  = C4 * w0a;  a[9]  = C4 * w0b;  a[10] = C5 * w0a;  a[11] = C5 * w0b;
        a[12] = C6 * w0a;  a[13] = C6 * w0b;  a[14] = C7 * w0a;  a[15] = C7 * w0b;
    }

    // ---- cycles 2..4: RY layer with all ring CNOTs fused in.
    //  order: [CX(7,0)]RY(q0) | RY(q1)+CX(0,1) | RY(q2)+CX(1,2) | ... | RY(q7)+CX(6,7)
#pragma unroll 1
    for (int cyc = 0; cyc < 3; ++cyc) {
        ryl2_cx<3>(a, c8[0], s8[0], lane);       // RY q0, pre-CX(7,0) ctrl R0
        ryr2_cx<3, 3>(a, c8[1], s8[1], lane);    // RY q1 (R3), post-CX ctrl q0 (L3)
        ryl2_post<2, 3>(a, c8[2], s8[2], lane);  // RY q2 (L2), post-CX ctrl q1 (R3)
        ryr2_cx<2, 2>(a, c8[3], s8[3], lane);    // RY q3 (R2), post-CX ctrl q2 (L2)
        ryl2_post<1, 2>(a, c8[4], s8[4], lane);  // RY q4 (L1), post-CX ctrl q3 (R2)
        ryr2_cx<1, 1>(a, c8[5], s8[5], lane);    // RY q5 (R1), post-CX ctrl q4 (L1)
        ryl2_post<0, 1>(a, c8[6], s8[6], lane);  // RY q6 (L0), post-CX ctrl q5 (R1)
        ryr2_cx<0, 0>(a, c8[7], s8[7], lane);    // RY q7 (R0), post-CX ctrl q6 (L0)
    }
    crl<0, 3>(a);                                // final pending CX(7,0)

    // ================= final (complex) stage =================
    float* ar = a;
    float ai[16];

    // ---- layer 0 CRX ----
    {
        float s0, c0;
        __sincosf(0.5f * crx_theta[0], &s0, &c0);
        crx_lr_r2c<3, 3>(ar, ai, c0, s0, lane);  // (q0,q1) real -> complex
        crx_lr<2, 2>(ar, ai, c0, s0, lane);      // (q2,q3)
        crx_lr<1, 1>(ar, ai, c0, s0, lane);      // (q4,q5)
        crx_lr<0, 0>(ar, ai, c0, s0, lane);      // (q6,q7)
        crx_rl<3, 2>(ar, ai, c0, s0);            // (q1,q2)
        crx_rl<2, 1>(ar, ai, c0, s0);            // (q3,q4)
        crx_rl<1, 0>(ar, ai, c0, s0);            // (q5,q6)
    }
    // ---- layer 0 U3 on qubits [1,3,5,7] (register-local) ----
    {
        float u00r,u01r,u01i,u10r,u10i,u11r,u11i;
        u3_coeffs(u3p, u00r,u01r,u01i,u10r,u10i,u11r,u11i);
        u3_reg<3>(ar, ai, u00r,u01r,u01i,u10r,u10i,u11r,u11i);  // q1
        u3_reg<2>(ar, ai, u00r,u01r,u01i,u10r,u10i,u11r,u11i);  // q3
        u3_reg<1>(ar, ai, u00r,u01r,u01i,u10r,u10i,u11r,u11i);  // q5
        u3_reg<0>(ar, ai, u00r,u01r,u01i,u10r,u10i,u11r,u11i);  // q7
    }
    // ---- layer 1 CRX on [1,3,5,7]: (1,3)(5,7) then (3,5) — register-local ----
    {
        float s1, c1;
        __sincosf(0.5f * crx_theta[1], &s1, &c1);
        crx_rr<3, 2>(ar, ai, c1, s1);    // (q1,q3)
        crx_rr<1, 0>(ar, ai, c1, s1);    // (q5,q7)
        crx_rr<2, 1>(ar, ai, c1, s1);    // (q3,q5)
    }

    // ---- layer 1 U3 on q3,q7 folded into the measurement:
    //      <Z after U3> = <M> with M = U† Z U = [[aM, b],[conj(b), -aM]].
    float aM, bMr, bMi;
    {
        float u00r,u01r,u01i,u10r,u10i,u11r,u11i;
        u3_coeffs(u3p + 3, u00r,u01r,u01i,u10r,u10i,u11r,u11i);
        aM  = u00r * u00r - (u10r * u10r + u10i * u10i);
        bMr = 2.0f * (u00r * u01r - (u10r * u11r + u10i * u11i));
        bMi = 2.0f * (u00r * u01i - (u10r * u11i - u10i * u11r));
    }
    // f0 = <M on q3> (reg bit 2), f1 = <M on q7> (reg bit 0).
    // Quads (r, r|1, r|4, r|5) cover both pairings with each |amp|^2 computed once.
    float f0 = 0.0f, f1 = 0.0f;
#pragma unroll
    for (int qd = 0; qd < 4; ++qd) {
        const int r = ((qd >> 1) << 3) | ((qd & 1) << 1);   // 0, 2, 8, 10
        const int rA = r, rB = r | 1, rC = r | 4, rD = r | 5;
        const float mA = fmaf(ar[rA], ar[rA], ai[rA] * ai[rA]);
        const float mB = fmaf(ar[rB], ar[rB], ai[rB] * ai[rB]);
        const float mC = fmaf(ar[rC], ar[rC], ai[rC] * ai[rC]);
        const float mD = fmaf(ar[rD], ar[rD], ai[rD] * ai[rD]);
        // f0 pairs: (A,C), (B,D)   [z0 = bit2-clear, z1 = bit2-set]
        {
            float wre = fmaf(ai[rA], ai[rC], ar[rA] * ar[rC]);
            float wim = fmaf(-ai[rA], ar[rC], ar[rA] * ai[rC]);
            f0 = fmaf(aM, mA - mC, f0);
            f0 = fmaf(bMr, wre, f0);
            f0 = fmaf(-bMi, wim, f0);
            wre = fmaf(ai[rB], ai[rD], ar[rB] * ar[rD]);
            wim = fmaf(-ai[rB], ar[rD], ar[rB] * ai[rD]);
            f0 = fmaf(aM, mB - mD, f0);
            f0 = fmaf(bMr, wre, f0);
            f0 = fmaf(-bMi, wim, f0);
        }
        // f1 pairs: (A,B), (C,D)   [z0 = bit0-clear, z1 = bit0-set]
        {
            float wre = fmaf(ai[rA], ai[rB], ar[rA] * ar[rB]);
            float wim = fmaf(-ai[rA], ar[rB], ar[rA] * ai[rB]);
            f1 = fmaf(aM, mA - mB, f1);
            f1 = fmaf(bMr, wre, f1);
            f1 = fmaf(-bMi, wim, f1);
            wre = fmaf(ai[rC], ai[rD], ar[rC] * ar[rD]);
            wim = fmaf(-ai[rC], ar[rD], ar[rC] * ai[rD]);
            f1 = fmaf(aM, mC - mD, f1);
            f1 = fmaf(bMr, wre, f1);
            f1 = fmaf(-bMi, wim, f1);
        }
    }
#pragma unroll
    for (int m = 8; m >= 1; m >>= 1) {   // stays within half-warp
        f0 += shx(f0, m);
        f1 += shx(f1, m);
    }

    // ---- MLP head: sigmoid(tanh(f @ w1 + b1) @ w2 + b2), tanh spread over 10 lanes ----
    float contrib = 0.0f;
    if (sl < 10) {
        float h = tanhf(fmaf(f0, w1[sl], fmaf(f1, w1[10 + sl], b1[sl])));
        contrib = h * w2[sl];
    }
#pragma unroll
    for (int m = 8; m >= 1; m >>= 1) contrib += shx(contrib, m);
    if (sl == 0 && e < nB) {
        out[e] = 1.0f / (1.0f + __expf(-(contrib + b2[0])));
    }
}

extern "C" void kernel_launch(void* const* d_in, const int* in_sizes, int n_in,
                              void* d_out, int out_size) {
    const float* x         = (const float*)d_in[0];
    const float* crx_theta = (const float*)d_in[1];
    const float* u3_params = (const float*)d_in[2];
    const float* w1        = (const float*)d_in[3];
    const float* b1        = (const float*)d_in[4];
    const float* w2        = (const float*)d_in[5];
    const float* b2        = (const float*)d_in[6];
    float* out = (float*)d_out;

    const int nB = out_size;                  // (B, 1) output -> B batch elements
    const int threads = 256;                  // 8 warps/block, 2 elements per warp
    const int nWarps = (nB + 1) / 2;
    const int blocks = (nWarps * 32 + threads - 1) / threads;
    qcnn_kernel<<<blocks, threads>>>(x, crx_theta, u3_params, w1, b1, w2, b2, out, nB);
}